// round 2
// baseline (speedup 1.0000x reference)
#include <cuda_runtime.h>

#define N_NODESC 100000
#define NFEAT    512
#define HID      64
#define NCLS     40
#define N_EDGESC 3200000
#define KPROP    10

#define SCAN_B 512
#define NSB ((N_NODESC + SCAN_B - 1) / SCAN_B)   // 196

struct __align__(8) Edge { int src; float w; };

// ---- static scratch (no allocations allowed) ----
__device__ int   g_is64;
__device__ int   g_indeg[N_NODESC];
__device__ float g_dinv[N_NODESC];
__device__ int   g_offs[N_NODESC + 1];
__device__ int   g_cursor[N_NODESC];
__device__ int   g_bsum[NSB];
__device__ Edge  g_csr[N_EDGESC];
__device__ float g_h1[(size_t)N_NODESC * HID];
__device__ float g_bufA[(size_t)N_NODESC * NCLS];
__device__ float g_bufB[(size_t)N_NODESC * NCLS];
__device__ float g_out[(size_t)N_NODESC * NCLS];

// ---------------- dtype detection: int64 edge_index has zero high words ----
__global__ void k_detect(const int* __restrict__ ei) {
    int nz = 0;
    for (int t = threadIdx.x; t < 64; t += 32)
        nz |= (ei[2 * t + 1] != 0);
    unsigned b = __ballot_sync(0xffffffffu, nz);
    if (threadIdx.x == 0) g_is64 = (b == 0u);   // all high words zero -> int64
}

__device__ __forceinline__ int load_src(const int* ei, int e, int is64) {
    return is64 ? ei[2 * e] : ei[e];
}
__device__ __forceinline__ int load_dst(const int* ei, int e, int is64) {
    return is64 ? ei[2 * (N_EDGESC + e)] : ei[N_EDGESC + e];
}

// ---------------- preprocessing ----------------
__global__ void k_zero() {
    int i = blockIdx.x * blockDim.x + threadIdx.x;
    if (i < N_NODESC) g_indeg[i] = 0;
}

__global__ void k_count(const int* __restrict__ ei) {
    int e = blockIdx.x * blockDim.x + threadIdx.x;
    if (e < N_EDGESC) {
        int dst = load_dst(ei, e, g_is64);
        if ((unsigned)dst < N_NODESC) atomicAdd(&g_indeg[dst], 1);
    }
}

__global__ void k_dinv() {
    int i = blockIdx.x * blockDim.x + threadIdx.x;
    if (i < N_NODESC) g_dinv[i] = rsqrtf((float)(g_indeg[i] + 1));  // +1 self loop
}

__global__ void k_scan1() {
    __shared__ int s[SCAN_B];
    int i = blockIdx.x * SCAN_B + threadIdx.x;
    int v = (i < N_NODESC) ? g_indeg[i] : 0;
    s[threadIdx.x] = v;
    __syncthreads();
    #pragma unroll
    for (int off = 1; off < SCAN_B; off <<= 1) {
        int t = (threadIdx.x >= off) ? s[threadIdx.x - off] : 0;
        __syncthreads();
        s[threadIdx.x] += t;
        __syncthreads();
    }
    if (i < N_NODESC) g_offs[i] = s[threadIdx.x] - v;   // exclusive within block
    if (threadIdx.x == SCAN_B - 1) g_bsum[blockIdx.x] = s[SCAN_B - 1];
}

__global__ void k_scan2() {
    int acc = 0;
    for (int b = 0; b < NSB; b++) { int v = g_bsum[b]; g_bsum[b] = acc; acc += v; }
    g_offs[N_NODESC] = acc;
}

__global__ void k_scan3() {
    int i = blockIdx.x * blockDim.x + threadIdx.x;
    if (i < N_NODESC) {
        int o = g_offs[i] + g_bsum[i >> 9];   // 512 per scan block
        g_offs[i] = o;
        g_cursor[i] = o;
    }
}

__global__ void k_scatter(const int* __restrict__ ei) {
    int e = blockIdx.x * blockDim.x + threadIdx.x;
    if (e < N_EDGESC) {
        int is64 = g_is64;
        int src = load_src(ei, e, is64);
        int dst = load_dst(ei, e, is64);
        if ((unsigned)src >= N_NODESC || (unsigned)dst >= N_NODESC) return;
        int p = atomicAdd(&g_cursor[dst], 1);
        if ((unsigned)p < N_EDGESC) {
            Edge ed; ed.src = src; ed.w = g_dinv[src];
            g_csr[p] = ed;
        }
    }
}

// ---------------- MLP layer 1 : h1 = relu(x @ w1 + b1) ----------------
#define BM 128
#define BN 64
#define BK 32

__global__ __launch_bounds__(256) void k_mlp1(const float* __restrict__ x,
                                              const float* __restrict__ w1,
                                              const float* __restrict__ b1) {
    __shared__ float As[BK][BM + 4];   // transposed A tile, padded
    __shared__ float Bs[BK][BN];
    int tid = threadIdx.x;
    int tc = tid & 15, tr = tid >> 4;
    int r0 = tr * 8, c0 = tc * 4;
    int blockRow = blockIdx.x * BM;

    float acc[8][4];
    #pragma unroll
    for (int i = 0; i < 8; i++)
        #pragma unroll
        for (int j = 0; j < 4; j++) acc[i][j] = 0.f;

    for (int kk = 0; kk < NFEAT; kk += BK) {
        #pragma unroll
        for (int i = 0; i < 4; i++) {
            int f = tid + 256 * i;
            int row = f >> 3;
            int c4 = f & 7;
            int grow = blockRow + row;
            float4 v = make_float4(0.f, 0.f, 0.f, 0.f);
            if (grow < N_NODESC)
                v = *(const float4*)&x[(size_t)grow * NFEAT + kk + c4 * 4];
            As[c4 * 4 + 0][row] = v.x;
            As[c4 * 4 + 1][row] = v.y;
            As[c4 * 4 + 2][row] = v.z;
            As[c4 * 4 + 3][row] = v.w;
        }
        #pragma unroll
        for (int i = 0; i < 2; i++) {
            int f = tid + 256 * i;
            int row = f >> 4;
            int c4 = f & 15;
            float4 v = *(const float4*)&w1[(size_t)(kk + row) * HID + c4 * 4];
            *(float4*)&Bs[row][c4 * 4] = v;
        }
        __syncthreads();
        #pragma unroll
        for (int k = 0; k < BK; k++) {
            float a[8], b[4];
            #pragma unroll
            for (int i = 0; i < 8; i++) a[i] = As[k][r0 + i];
            #pragma unroll
            for (int j = 0; j < 4; j++) b[j] = Bs[k][c0 + j];
            #pragma unroll
            for (int i = 0; i < 8; i++)
                #pragma unroll
                for (int j = 0; j < 4; j++)
                    acc[i][j] = fmaf(a[i], b[j], acc[i][j]);
        }
        __syncthreads();
    }
    float4 bb = *(const float4*)&b1[c0];
    #pragma unroll
    for (int i = 0; i < 8; i++) {
        int grow = blockRow + r0 + i;
        if (grow < N_NODESC) {
            float4 o;
            o.x = fmaxf(acc[i][0] + bb.x, 0.f);
            o.y = fmaxf(acc[i][1] + bb.y, 0.f);
            o.z = fmaxf(acc[i][2] + bb.z, 0.f);
            o.w = fmaxf(acc[i][3] + bb.w, 0.f);
            *(float4*)&g_h1[(size_t)grow * HID + c0] = o;
        }
    }
}

// ---------------- MLP layer 2 (+ init out = gamma0*h2, cur = h2) ----------------
__global__ __launch_bounds__(128) void k_mlp2(const float* __restrict__ w2,
                                              const float* __restrict__ b2,
                                              const float* __restrict__ temp) {
    __shared__ float ws[HID * NCLS];
    __shared__ float bs[NCLS];
    __shared__ float hs[128 * (HID + 1)];
    int tid = threadIdx.x;
    for (int i = tid; i < HID * NCLS; i += 128) ws[i] = w2[i];
    if (tid < NCLS) bs[tid] = b2[tid];
    int base = blockIdx.x * 128;
    #pragma unroll
    for (int i = 0; i < HID; i++) {
        int f = tid + 128 * i;
        int row = f >> 6, c = f & 63;
        int g = base + row;
        hs[row * (HID + 1) + c] = (g < N_NODESC) ? g_h1[(size_t)g * HID + c] : 0.f;
    }
    __syncthreads();
    int node = base + tid;
    if (node >= N_NODESC) return;
    float acc[NCLS];
    #pragma unroll
    for (int c = 0; c < NCLS; c++) acc[c] = bs[c];
    #pragma unroll 4
    for (int j = 0; j < HID; j++) {
        float hj = hs[tid * (HID + 1) + j];
        #pragma unroll
        for (int c = 0; c < NCLS; c++) acc[c] = fmaf(hj, ws[j * NCLS + c], acc[c]);
    }
    float g0 = fmaxf(temp[0], 0.f);
    size_t o = (size_t)node * NCLS;
    #pragma unroll
    for (int c = 0; c < NCLS; c++) {
        g_bufA[o + c] = acc[c];
        g_out[o + c] = g0 * acc[c];
    }
}

// ---------------- propagation: 8 lanes/node, 5 channels/lane ----------------
__global__ __launch_bounds__(256) void k_gather(int parity, int kstep,
                                                const float* __restrict__ temp) {
    const float* __restrict__ cur = parity ? g_bufB : g_bufA;
    float* __restrict__ nxt = parity ? g_bufA : g_bufB;
    int t = blockIdx.x * 256 + threadIdx.x;
    int node = t >> 3;
    int lane = t & 7;
    if (node >= N_NODESC) return;
    int beg = g_offs[node];
    int end = g_offs[node + 1];
    float a0 = 0.f, a1 = 0.f, a2 = 0.f, a3 = 0.f, a4 = 0.f;
    for (int e = beg; e < end; ++e) {
        Edge ed = g_csr[e];
        const float* row = cur + (size_t)ed.src * NCLS;
        float w = ed.w;
        a0 = fmaf(w, __ldg(row + lane), a0);
        a1 = fmaf(w, __ldg(row + lane + 8), a1);
        a2 = fmaf(w, __ldg(row + lane + 16), a2);
        a3 = fmaf(w, __ldg(row + lane + 24), a3);
        a4 = fmaf(w, __ldg(row + lane + 32), a4);
    }
    float di = g_dinv[node];
    const float* me = cur + (size_t)node * NCLS;
    float gamma = fmaxf(temp[kstep + 1], 0.f);
    size_t o = (size_t)node * NCLS + lane;
    float r;
    r = di * (a0 + di * me[lane]);      nxt[o]      = r; g_out[o]      += gamma * r;
    r = di * (a1 + di * me[lane + 8]);  nxt[o + 8]  = r; g_out[o + 8]  += gamma * r;
    r = di * (a2 + di * me[lane + 16]); nxt[o + 16] = r; g_out[o + 16] += gamma * r;
    r = di * (a3 + di * me[lane + 24]); nxt[o + 24] = r; g_out[o + 24] += gamma * r;
    r = di * (a4 + di * me[lane + 32]); nxt[o + 32] = r; g_out[o + 32] += gamma * r;
}

// ---------------- log_softmax ----------------
__global__ void k_lsm(float* __restrict__ out) {
    int node = blockIdx.x * blockDim.x + threadIdx.x;
    if (node >= N_NODESC) return;
    float v[NCLS];
    const float4* p = (const float4*)(g_out + (size_t)node * NCLS);
    #pragma unroll
    for (int i = 0; i < NCLS / 4; i++) {
        float4 q = p[i];
        v[4 * i] = q.x; v[4 * i + 1] = q.y; v[4 * i + 2] = q.z; v[4 * i + 3] = q.w;
    }
    float m = -1e30f;
    #pragma unroll
    for (int c = 0; c < NCLS; c++) m = fmaxf(m, v[c]);
    float s = 0.f;
    #pragma unroll
    for (int c = 0; c < NCLS; c++) s += expf(v[c] - m);
    float l = m + logf(s);
    float4* q = (float4*)(out + (size_t)node * NCLS);
    #pragma unroll
    for (int i = 0; i < NCLS / 4; i++) {
        float4 w;
        w.x = v[4 * i] - l; w.y = v[4 * i + 1] - l;
        w.z = v[4 * i + 2] - l; w.w = v[4 * i + 3] - l;
        q[i] = w;
    }
}

extern "C" void kernel_launch(void* const* d_in, const int* in_sizes, int n_in,
                              void* d_out, int out_size) {
    const float* x    = (const float*)d_in[0];
    const int*   ei   = (const int*)d_in[1];     // int32 or int64 (auto-detected)
    const float* w1   = (const float*)d_in[2];
    const float* b1   = (const float*)d_in[3];
    const float* w2   = (const float*)d_in[4];
    const float* b2   = (const float*)d_in[5];
    const float* temp = (const float*)d_in[6];
    float* out = (float*)d_out;

    int nb_nodes = (N_NODESC + 255) / 256;
    int nb_edges = (N_EDGESC + 255) / 256;

    k_detect<<<1, 32>>>(ei);
    k_zero<<<nb_nodes, 256>>>();
    k_count<<<nb_edges, 256>>>(ei);
    k_dinv<<<nb_nodes, 256>>>();
    k_scan1<<<NSB, SCAN_B>>>();
    k_scan2<<<1, 1>>>();
    k_scan3<<<nb_nodes, 256>>>();
    k_scatter<<<nb_edges, 256>>>(ei);

    k_mlp1<<<(N_NODESC + BM - 1) / BM, 256>>>(x, w1, b1);
    k_mlp2<<<(N_NODESC + 127) / 128, 128>>>(w2, b2, temp);

    for (int k = 0; k < KPROP; k++)
        k_gather<<<(N_NODESC * 8 + 255) / 256, 256>>>(k & 1, k, temp);

    k_lsm<<<nb_nodes, 256>>>(out);
}

// round 3
// speedup vs baseline: 1.1095x; 1.1095x over previous
#include <cuda_runtime.h>
#include <cuda_fp16.h>

#define N_NODESC 100000
#define NFEAT    512
#define HID      64
#define NCLS     40
#define N_EDGESC 3200000
#define KPROP    10
#define H2ROW    (NCLS / 2)   // 20 half2 per row

#define SCAN_B 512
#define NSB ((N_NODESC + SCAN_B - 1) / SCAN_B)   // 196

struct __align__(8) Edge { int src; float w; };

// ---- static scratch (no allocations allowed) ----
__device__ int     g_is64;
__device__ int     g_indeg[N_NODESC];
__device__ float   g_dinv[N_NODESC];
__device__ int     g_offs[N_NODESC + 1];
__device__ int     g_cursor[N_NODESC];
__device__ int     g_bsum[NSB];
__device__ Edge    g_csr[N_EDGESC];
__device__ float   g_h1[(size_t)N_NODESC * HID];
__device__ __half2 g_bufA[(size_t)N_NODESC * H2ROW];
__device__ __half2 g_bufB[(size_t)N_NODESC * H2ROW];
__device__ float   g_out[(size_t)N_NODESC * NCLS];

// ---------------- dtype detection: int64 edge_index has zero high words ----
__global__ void k_detect(const int* __restrict__ ei) {
    int nz = 0;
    for (int t = threadIdx.x; t < 64; t += 32)
        nz |= (ei[2 * t + 1] != 0);
    unsigned b = __ballot_sync(0xffffffffu, nz);
    if (threadIdx.x == 0) g_is64 = (b == 0u);   // all high words zero -> int64
}

__device__ __forceinline__ int load_src(const int* ei, int e, int is64) {
    return is64 ? ei[2 * e] : ei[e];
}
__device__ __forceinline__ int load_dst(const int* ei, int e, int is64) {
    return is64 ? ei[2 * (N_EDGESC + e)] : ei[N_EDGESC + e];
}

// ---------------- preprocessing ----------------
__global__ void k_zero() {
    int i = blockIdx.x * blockDim.x + threadIdx.x;
    if (i < N_NODESC) g_indeg[i] = 0;
}

__global__ void k_count(const int* __restrict__ ei) {
    int e = blockIdx.x * blockDim.x + threadIdx.x;
    if (e < N_EDGESC) {
        int dst = load_dst(ei, e, g_is64);
        if ((unsigned)dst < N_NODESC) atomicAdd(&g_indeg[dst], 1);
    }
}

__global__ void k_dinv() {
    int i = blockIdx.x * blockDim.x + threadIdx.x;
    if (i < N_NODESC) g_dinv[i] = rsqrtf((float)(g_indeg[i] + 1));  // +1 self loop
}

__global__ void k_scan1() {
    __shared__ int s[SCAN_B];
    int i = blockIdx.x * SCAN_B + threadIdx.x;
    int v = (i < N_NODESC) ? g_indeg[i] : 0;
    s[threadIdx.x] = v;
    __syncthreads();
    #pragma unroll
    for (int off = 1; off < SCAN_B; off <<= 1) {
        int t = (threadIdx.x >= off) ? s[threadIdx.x - off] : 0;
        __syncthreads();
        s[threadIdx.x] += t;
        __syncthreads();
    }
    if (i < N_NODESC) g_offs[i] = s[threadIdx.x] - v;
    if (threadIdx.x == SCAN_B - 1) g_bsum[blockIdx.x] = s[SCAN_B - 1];
}

__global__ void k_scan2() {
    int acc = 0;
    for (int b = 0; b < NSB; b++) { int v = g_bsum[b]; g_bsum[b] = acc; acc += v; }
    g_offs[N_NODESC] = acc;
}

__global__ void k_scan3() {
    int i = blockIdx.x * blockDim.x + threadIdx.x;
    if (i < N_NODESC) {
        int o = g_offs[i] + g_bsum[i >> 9];
        g_offs[i] = o;
        g_cursor[i] = o;
    }
}

__global__ void k_scatter(const int* __restrict__ ei) {
    int e = blockIdx.x * blockDim.x + threadIdx.x;
    if (e < N_EDGESC) {
        int is64 = g_is64;
        int src = load_src(ei, e, is64);
        int dst = load_dst(ei, e, is64);
        if ((unsigned)src >= N_NODESC || (unsigned)dst >= N_NODESC) return;
        int p = atomicAdd(&g_cursor[dst], 1);
        if ((unsigned)p < N_EDGESC) {
            Edge ed; ed.src = src; ed.w = g_dinv[src];
            g_csr[p] = ed;
        }
    }
}

// ---------------- MLP layer 1 : h1 = relu(x @ w1 + b1) ----------------
#define BM 128
#define BN 64
#define BK 32

__global__ __launch_bounds__(256) void k_mlp1(const float* __restrict__ x,
                                              const float* __restrict__ w1,
                                              const float* __restrict__ b1) {
    __shared__ float As[BK][BM + 4];
    __shared__ float Bs[BK][BN];
    int tid = threadIdx.x;
    int tc = tid & 15, tr = tid >> 4;
    int r0 = tr * 8, c0 = tc * 4;
    int blockRow = blockIdx.x * BM;

    float acc[8][4];
    #pragma unroll
    for (int i = 0; i < 8; i++)
        #pragma unroll
        for (int j = 0; j < 4; j++) acc[i][j] = 0.f;

    for (int kk = 0; kk < NFEAT; kk += BK) {
        #pragma unroll
        for (int i = 0; i < 4; i++) {
            int f = tid + 256 * i;
            int row = f >> 3;
            int c4 = f & 7;
            int grow = blockRow + row;
            float4 v = make_float4(0.f, 0.f, 0.f, 0.f);
            if (grow < N_NODESC)
                v = *(const float4*)&x[(size_t)grow * NFEAT + kk + c4 * 4];
            As[c4 * 4 + 0][row] = v.x;
            As[c4 * 4 + 1][row] = v.y;
            As[c4 * 4 + 2][row] = v.z;
            As[c4 * 4 + 3][row] = v.w;
        }
        #pragma unroll
        for (int i = 0; i < 2; i++) {
            int f = tid + 256 * i;
            int row = f >> 4;
            int c4 = f & 15;
            float4 v = *(const float4*)&w1[(size_t)(kk + row) * HID + c4 * 4];
            *(float4*)&Bs[row][c4 * 4] = v;
        }
        __syncthreads();
        #pragma unroll
        for (int k = 0; k < BK; k++) {
            float a[8], b[4];
            #pragma unroll
            for (int i = 0; i < 8; i++) a[i] = As[k][r0 + i];
            #pragma unroll
            for (int j = 0; j < 4; j++) b[j] = Bs[k][c0 + j];
            #pragma unroll
            for (int i = 0; i < 8; i++)
                #pragma unroll
                for (int j = 0; j < 4; j++)
                    acc[i][j] = fmaf(a[i], b[j], acc[i][j]);
        }
        __syncthreads();
    }
    float4 bb = *(const float4*)&b1[c0];
    #pragma unroll
    for (int i = 0; i < 8; i++) {
        int grow = blockRow + r0 + i;
        if (grow < N_NODESC) {
            float4 o;
            o.x = fmaxf(acc[i][0] + bb.x, 0.f);
            o.y = fmaxf(acc[i][1] + bb.y, 0.f);
            o.z = fmaxf(acc[i][2] + bb.z, 0.f);
            o.w = fmaxf(acc[i][3] + bb.w, 0.f);
            *(float4*)&g_h1[(size_t)grow * HID + c0] = o;
        }
    }
}

// ---------------- MLP layer 2 (+ init out = gamma0*h2, cur = fp16(h2)) ------
__global__ __launch_bounds__(128) void k_mlp2(const float* __restrict__ w2,
                                              const float* __restrict__ b2,
                                              const float* __restrict__ temp) {
    __shared__ float ws[HID * NCLS];
    __shared__ float bs[NCLS];
    __shared__ float hs[128 * (HID + 1)];
    int tid = threadIdx.x;
    for (int i = tid; i < HID * NCLS; i += 128) ws[i] = w2[i];
    if (tid < NCLS) bs[tid] = b2[tid];
    int base = blockIdx.x * 128;
    #pragma unroll
    for (int i = 0; i < HID; i++) {
        int f = tid + 128 * i;
        int row = f >> 6, c = f & 63;
        int g = base + row;
        hs[row * (HID + 1) + c] = (g < N_NODESC) ? g_h1[(size_t)g * HID + c] : 0.f;
    }
    __syncthreads();
    int node = base + tid;
    if (node >= N_NODESC) return;
    float acc[NCLS];
    #pragma unroll
    for (int c = 0; c < NCLS; c++) acc[c] = bs[c];
    #pragma unroll 4
    for (int j = 0; j < HID; j++) {
        float hj = hs[tid * (HID + 1) + j];
        #pragma unroll
        for (int c = 0; c < NCLS; c++) acc[c] = fmaf(hj, ws[j * NCLS + c], acc[c]);
    }
    float g0 = fmaxf(temp[0], 0.f);
    size_t o = (size_t)node * NCLS;
    __half2* cw = g_bufA + (size_t)node * H2ROW;
    #pragma unroll
    for (int i = 0; i < H2ROW; i++)
        cw[i] = __floats2half2_rn(acc[2 * i], acc[2 * i + 1]);
    #pragma unroll
    for (int c = 0; c < NCLS; c++) g_out[o + c] = g0 * acc[c];
}

// ------- propagation: 4 lanes/node, 5 half2 (=10 channels) per lane --------
__global__ __launch_bounds__(256) void k_gather(int parity, int kstep,
                                                const float* __restrict__ temp) {
    const __half2* __restrict__ cur = parity ? g_bufB : g_bufA;
    __half2* __restrict__ nxt = parity ? g_bufA : g_bufB;
    int t = blockIdx.x * 256 + threadIdx.x;
    int node = t >> 2;
    int lane = t & 3;
    if (node >= N_NODESC) return;
    int beg = g_offs[node];
    int end = g_offs[node + 1];
    float2 a0 = make_float2(0.f, 0.f), a1 = a0, a2 = a0, a3 = a0, a4 = a0;
    for (int e = beg; e < end; ++e) {
        Edge ed = g_csr[e];
        const __half2* row = cur + (size_t)ed.src * H2ROW + lane;
        float w = ed.w;
        float2 v;
        v = __half22float2(__ldg(row));      a0.x = fmaf(w, v.x, a0.x); a0.y = fmaf(w, v.y, a0.y);
        v = __half22float2(__ldg(row + 4));  a1.x = fmaf(w, v.x, a1.x); a1.y = fmaf(w, v.y, a1.y);
        v = __half22float2(__ldg(row + 8));  a2.x = fmaf(w, v.x, a2.x); a2.y = fmaf(w, v.y, a2.y);
        v = __half22float2(__ldg(row + 12)); a3.x = fmaf(w, v.x, a3.x); a3.y = fmaf(w, v.y, a3.y);
        v = __half22float2(__ldg(row + 16)); a4.x = fmaf(w, v.x, a4.x); a4.y = fmaf(w, v.y, a4.y);
    }
    float di = g_dinv[node];
    float di2 = di * di;
    const __half2* me = cur + (size_t)node * H2ROW + lane;
    __half2* nx = nxt + (size_t)node * H2ROW + lane;
    float gamma = fmaxf(temp[kstep + 1], 0.f);
    float2* orow = (float2*)(g_out + (size_t)node * NCLS) + lane;

    float2 m, r, o;
    #define STEP(J, ACC)                                                        \
        m = __half22float2(me[4 * J]);                                          \
        r.x = di * ACC.x + di2 * m.x;                                           \
        r.y = di * ACC.y + di2 * m.y;                                           \
        nx[4 * J] = __floats2half2_rn(r.x, r.y);                                \
        o = orow[4 * J];                                                        \
        o.x = fmaf(gamma, r.x, o.x);                                            \
        o.y = fmaf(gamma, r.y, o.y);                                            \
        orow[4 * J] = o;
    STEP(0, a0) STEP(1, a1) STEP(2, a2) STEP(3, a3) STEP(4, a4)
    #undef STEP
}

// ---------------- log_softmax ----------------
__global__ void k_lsm(float* __restrict__ out) {
    int node = blockIdx.x * blockDim.x + threadIdx.x;
    if (node >= N_NODESC) return;
    float v[NCLS];
    const float4* p = (const float4*)(g_out + (size_t)node * NCLS);
    #pragma unroll
    for (int i = 0; i < NCLS / 4; i++) {
        float4 q = p[i];
        v[4 * i] = q.x; v[4 * i + 1] = q.y; v[4 * i + 2] = q.z; v[4 * i + 3] = q.w;
    }
    float m = -1e30f;
    #pragma unroll
    for (int c = 0; c < NCLS; c++) m = fmaxf(m, v[c]);
    float s = 0.f;
    #pragma unroll
    for (int c = 0; c < NCLS; c++) s += expf(v[c] - m);
    float l = m + logf(s);
    float4* q = (float4*)(out + (size_t)node * NCLS);
    #pragma unroll
    for (int i = 0; i < NCLS / 4; i++) {
        float4 w;
        w.x = v[4 * i] - l; w.y = v[4 * i + 1] - l;
        w.z = v[4 * i + 2] - l; w.w = v[4 * i + 3] - l;
        q[i] = w;
    }
}

extern "C" void kernel_launch(void* const* d_in, const int* in_sizes, int n_in,
                              void* d_out, int out_size) {
    const float* x    = (const float*)d_in[0];
    const int*   ei   = (const int*)d_in[1];     // int32 or int64 (auto-detected)
    const float* w1   = (const float*)d_in[2];
    const float* b1   = (const float*)d_in[3];
    const float* w2   = (const float*)d_in[4];
    const float* b2   = (const float*)d_in[5];
    const float* temp = (const float*)d_in[6];
    float* out = (float*)d_out;

    int nb_nodes = (N_NODESC + 255) / 256;
    int nb_edges = (N_EDGESC + 255) / 256;

    k_detect<<<1, 32>>>(ei);
    k_zero<<<nb_nodes, 256>>>();
    k_count<<<nb_edges, 256>>>(ei);
    k_dinv<<<nb_nodes, 256>>>();
    k_scan1<<<NSB, SCAN_B>>>();
    k_scan2<<<1, 1>>>();
    k_scan3<<<nb_nodes, 256>>>();
    k_scatter<<<nb_edges, 256>>>(ei);

    k_mlp1<<<(N_NODESC + BM - 1) / BM, 256>>>(x, w1, b1);
    k_mlp2<<<(N_NODESC + 127) / 128, 128>>>(w2, b2, temp);

    for (int k = 0; k < KPROP; k++)
        k_gather<<<(N_NODESC * 4 + 255) / 256, 256>>>(k & 1, k, temp);

    k_lsm<<<nb_nodes, 256>>>(out);
}

// round 5
// speedup vs baseline: 1.5889x; 1.4321x over previous
#include <cuda_runtime.h>
#include <cuda_fp16.h>
#include <cstdint>

#define N_NODESC 100000
#define NFEAT    512
#define HID      64
#define NCLS     40
#define N_EDGESC 3200000
#define KPROP    10
#define H2ROW    (NCLS / 2)          // 20 half2 = 80B per node row
#define ROWB     80

#define SCAN_B 512
#define NSB ((N_NODESC + SCAN_B - 1) / SCAN_B)   // 196

// ---- static scratch (no allocations allowed) ----
__device__ int     g_is64;
__device__ int     g_indeg[N_NODESC];
__device__ float   g_dinv[N_NODESC];
__device__ int     g_offs[N_NODESC + 1];
__device__ int     g_cursor[N_NODESC];
__device__ int     g_bsum[NSB];
__device__ int     g_src[N_EDGESC];
__device__ float   g_h1[(size_t)N_NODESC * HID];
__device__ __half2 g_hist[(size_t)(KPROP + 1) * N_NODESC * H2ROW];   // s_0..s_10

// ---------------- dtype detection: int64 edge_index has zero high words ----
__global__ void k_detect(const int* __restrict__ ei) {
    int nz = 0;
    for (int t = threadIdx.x; t < 64; t += 32)
        nz |= (ei[2 * t + 1] != 0);
    unsigned b = __ballot_sync(0xffffffffu, nz);
    if (threadIdx.x == 0) g_is64 = (b == 0u);
}

__device__ __forceinline__ int load_src(const int* ei, int e, int is64) {
    return is64 ? ei[2 * e] : ei[e];
}
__device__ __forceinline__ int load_dst(const int* ei, int e, int is64) {
    return is64 ? ei[2 * (N_EDGESC + e)] : ei[N_EDGESC + e];
}

// ---------------- preprocessing ----------------
__global__ void k_zero() {
    int i = blockIdx.x * blockDim.x + threadIdx.x;
    if (i < N_NODESC) g_indeg[i] = 0;
}

__global__ void k_count(const int* __restrict__ ei) {
    int e = blockIdx.x * blockDim.x + threadIdx.x;
    if (e < N_EDGESC) {
        int dst = load_dst(ei, e, g_is64);
        if ((unsigned)dst < N_NODESC) atomicAdd(&g_indeg[dst], 1);
    }
}

__global__ void k_scan1() {
    __shared__ int s[SCAN_B];
    int i = blockIdx.x * SCAN_B + threadIdx.x;
    int v = (i < N_NODESC) ? g_indeg[i] : 0;
    s[threadIdx.x] = v;
    __syncthreads();
    #pragma unroll
    for (int off = 1; off < SCAN_B; off <<= 1) {
        int t = (threadIdx.x >= off) ? s[threadIdx.x - off] : 0;
        __syncthreads();
        s[threadIdx.x] += t;
        __syncthreads();
    }
    if (i < N_NODESC) g_offs[i] = s[threadIdx.x] - v;
    if (threadIdx.x == SCAN_B - 1) g_bsum[blockIdx.x] = s[SCAN_B - 1];
}

// parallel exclusive scan of the 196 block sums (one 256-thread block)
__global__ void k_scan2p() {
    __shared__ int s[256];
    int i = threadIdx.x;
    int v = (i < NSB) ? g_bsum[i] : 0;
    s[i] = v;
    __syncthreads();
    #pragma unroll
    for (int off = 1; off < 256; off <<= 1) {
        int t = (i >= off) ? s[i - off] : 0;
        __syncthreads();
        s[i] += t;
        __syncthreads();
    }
    if (i < NSB) g_bsum[i] = s[i] - v;
    if (i == 255) g_offs[N_NODESC] = s[255];
}

__global__ void k_scan3() {   // offsets + cursor + dinv
    int i = blockIdx.x * blockDim.x + threadIdx.x;
    if (i < N_NODESC) {
        int o = g_offs[i] + g_bsum[i >> 9];
        g_offs[i] = o;
        g_cursor[i] = o;
        g_dinv[i] = rsqrtf((float)(g_indeg[i] + 1));   // +1 self loop
    }
}

__global__ void k_scatter(const int* __restrict__ ei) {
    int e = blockIdx.x * blockDim.x + threadIdx.x;
    if (e < N_EDGESC) {
        int is64 = g_is64;
        int src = load_src(ei, e, is64);
        int dst = load_dst(ei, e, is64);
        if ((unsigned)src >= N_NODESC || (unsigned)dst >= N_NODESC) return;
        int p = atomicAdd(&g_cursor[dst], 1);
        if ((unsigned)p < N_EDGESC) g_src[p] = src;
    }
}

// ---------------- MLP layer 1 : h1 = relu(x @ w1 + b1), FFMA SGEMM ----------------
#define BM 128
#define BN 64
#define BK 32

__global__ __launch_bounds__(256) void k_mlp1(const float* __restrict__ x,
                                              const float* __restrict__ w1,
                                              const float* __restrict__ b1) {
    __shared__ float As[BK][BM + 4];
    __shared__ float Bs[BK][BN];
    int tid = threadIdx.x;
    int tc = tid & 15, tr = tid >> 4;
    int r0 = tr * 8, c0 = tc * 4;
    int blockRow = blockIdx.x * BM;

    float acc[8][4];
    #pragma unroll
    for (int i = 0; i < 8; i++)
        #pragma unroll
        for (int j = 0; j < 4; j++) acc[i][j] = 0.f;

    for (int kk = 0; kk < NFEAT; kk += BK) {
        #pragma unroll
        for (int i = 0; i < 4; i++) {
            int f = tid + 256 * i;
            int row = f >> 3;
            int c4 = f & 7;
            int grow = blockRow + row;
            float4 v = make_float4(0.f, 0.f, 0.f, 0.f);
            if (grow < N_NODESC)
                v = *(const float4*)&x[(size_t)grow * NFEAT + kk + c4 * 4];
            As[c4 * 4 + 0][row] = v.x;
            As[c4 * 4 + 1][row] = v.y;
            As[c4 * 4 + 2][row] = v.z;
            As[c4 * 4 + 3][row] = v.w;
        }
        #pragma unroll
        for (int i = 0; i < 2; i++) {
            int f = tid + 256 * i;
            int row = f >> 4;
            int c4 = f & 15;
            float4 v = *(const float4*)&w1[(size_t)(kk + row) * HID + c4 * 4];
            *(float4*)&Bs[row][c4 * 4] = v;
        }
        __syncthreads();
        #pragma unroll
        for (int k = 0; k < BK; k++) {
            float a[8], b[4];
            #pragma unroll
            for (int i = 0; i < 8; i++) a[i] = As[k][r0 + i];
            #pragma unroll
            for (int j = 0; j < 4; j++) b[j] = Bs[k][c0 + j];
            #pragma unroll
            for (int i = 0; i < 8; i++)
                #pragma unroll
                for (int j = 0; j < 4; j++)
                    acc[i][j] = fmaf(a[i], b[j], acc[i][j]);
        }
        __syncthreads();
    }
    float4 bb = *(const float4*)&b1[c0];
    #pragma unroll
    for (int i = 0; i < 8; i++) {
        int grow = blockRow + r0 + i;
        if (grow < N_NODESC) {
            float4 o;
            o.x = fmaxf(acc[i][0] + bb.x, 0.f);
            o.y = fmaxf(acc[i][1] + bb.y, 0.f);
            o.z = fmaxf(acc[i][2] + bb.z, 0.f);
            o.w = fmaxf(acc[i][3] + bb.w, 0.f);
            *(float4*)&g_h1[(size_t)grow * HID + c0] = o;
        }
    }
}

// ------- MLP layer 2 : h2 = h1 @ w2 + b2 ; write s_0 = dinv * h2 (fp16) -------
__global__ __launch_bounds__(128) void k_mlp2(const float* __restrict__ w2,
                                              const float* __restrict__ b2) {
    __shared__ float ws[HID * NCLS];
    __shared__ float bs[NCLS];
    __shared__ float hs[128 * (HID + 1)];
    int tid = threadIdx.x;
    for (int i = tid; i < HID * NCLS; i += 128) ws[i] = w2[i];
    if (tid < NCLS) bs[tid] = b2[tid];
    int base = blockIdx.x * 128;
    #pragma unroll
    for (int i = 0; i < HID; i++) {
        int f = tid + 128 * i;
        int row = f >> 6, c = f & 63;
        int g = base + row;
        hs[row * (HID + 1) + c] = (g < N_NODESC) ? g_h1[(size_t)g * HID + c] : 0.f;
    }
    __syncthreads();
    int node = base + tid;
    if (node >= N_NODESC) return;
    float acc[NCLS];
    #pragma unroll
    for (int c = 0; c < NCLS; c++) acc[c] = bs[c];
    #pragma unroll 4
    for (int j = 0; j < HID; j++) {
        float hj = hs[tid * (HID + 1) + j];
        #pragma unroll
        for (int c = 0; c < NCLS; c++) acc[c] = fmaf(hj, ws[j * NCLS + c], acc[c]);
    }
    float di = g_dinv[node];
    __half2* s0 = g_hist + (size_t)node * H2ROW;
    #pragma unroll
    for (int i = 0; i < H2ROW; i++)
        s0[i] = __floats2half2_rn(di * acc[2 * i], di * acc[2 * i + 1]);
}

// ------- propagation (s-form): s_{k+1}[d] = dinv[d]^2 * (sum_e s_k[src] + s_k[d])
// 5 lanes/node, one LDG.128 (8 channels) per lane, no weights, no out-accum.
__global__ __launch_bounds__(320) void k_gather(int kstep) {
    const char* __restrict__ cur = (const char*)(g_hist + (size_t)kstep * N_NODESC * H2ROW);
    char* __restrict__ nxt = (char*)(g_hist + (size_t)(kstep + 1) * N_NODESC * H2ROW);
    int t = blockIdx.x * 320 + threadIdx.x;
    int node = t / 5;
    int lane = t - node * 5;
    if (node >= N_NODESC) return;
    int beg = g_offs[node];
    int end = g_offs[node + 1];
    int lb = lane * 16;
    float a0 = 0.f, a1 = 0.f, a2 = 0.f, a3 = 0.f,
          a4 = 0.f, a5 = 0.f, a6 = 0.f, a7 = 0.f;
    #pragma unroll 4
    for (int e = beg; e < end; ++e) {
        int src = __ldg(&g_src[e]);
        uint4 p = __ldg((const uint4*)(cur + (size_t)src * ROWB + lb));
        float2 v;
        v = __half22float2(*(__half2*)&p.x); a0 += v.x; a1 += v.y;
        v = __half22float2(*(__half2*)&p.y); a2 += v.x; a3 += v.y;
        v = __half22float2(*(__half2*)&p.z); a4 += v.x; a5 += v.y;
        v = __half22float2(*(__half2*)&p.w); a6 += v.x; a7 += v.y;
    }
    float di = g_dinv[node];
    float di2 = di * di;
    uint4 mr = *(const uint4*)(cur + (size_t)node * ROWB + lb);
    float2 m;
    float r[8];
    m = __half22float2(*(__half2*)&mr.x); r[0] = di2 * (a0 + m.x); r[1] = di2 * (a1 + m.y);
    m = __half22float2(*(__half2*)&mr.y); r[2] = di2 * (a2 + m.x); r[3] = di2 * (a3 + m.y);
    m = __half22float2(*(__half2*)&mr.z); r[4] = di2 * (a4 + m.x); r[5] = di2 * (a5 + m.y);
    m = __half22float2(*(__half2*)&mr.w); r[6] = di2 * (a6 + m.x); r[7] = di2 * (a7 + m.y);
    uint4 nw;
    __half2 h;
    h = __floats2half2_rn(r[0], r[1]); nw.x = *(uint32_t*)&h;
    h = __floats2half2_rn(r[2], r[3]); nw.y = *(uint32_t*)&h;
    h = __floats2half2_rn(r[4], r[5]); nw.z = *(uint32_t*)&h;
    h = __floats2half2_rn(r[6], r[7]); nw.w = *(uint32_t*)&h;
    *(uint4*)(nxt + (size_t)node * ROWB + lb) = nw;
}

// ------- final: out = log_softmax( sqrtdeg * sum_k gamma_k * s_k ) -------
__global__ __launch_bounds__(256) void k_final(const float* __restrict__ temp,
                                               float* __restrict__ out) {
    int node = blockIdx.x * blockDim.x + threadIdx.x;
    if (node >= N_NODESC) return;
    float acc[NCLS];
    #pragma unroll
    for (int c = 0; c < NCLS; c++) acc[c] = 0.f;
    const char* base = (const char*)g_hist + (size_t)node * ROWB;
    #pragma unroll
    for (int k = 0; k <= KPROP; k++) {
        float gamma = fmaxf(__ldg(&temp[k]), 0.f);
        const char* row = base + (size_t)k * N_NODESC * ROWB;
        #pragma unroll
        for (int q = 0; q < 5; q++) {
            uint4 p = __ldg((const uint4*)(row + q * 16));
            float2 v;
            v = __half22float2(*(__half2*)&p.x);
            acc[q * 8 + 0] = fmaf(gamma, v.x, acc[q * 8 + 0]);
            acc[q * 8 + 1] = fmaf(gamma, v.y, acc[q * 8 + 1]);
            v = __half22float2(*(__half2*)&p.y);
            acc[q * 8 + 2] = fmaf(gamma, v.x, acc[q * 8 + 2]);
            acc[q * 8 + 3] = fmaf(gamma, v.y, acc[q * 8 + 3]);
            v = __half22float2(*(__half2*)&p.z);
            acc[q * 8 + 4] = fmaf(gamma, v.x, acc[q * 8 + 4]);
            acc[q * 8 + 5] = fmaf(gamma, v.y, acc[q * 8 + 5]);
            v = __half22float2(*(__half2*)&p.w);
            acc[q * 8 + 6] = fmaf(gamma, v.x, acc[q * 8 + 6]);
            acc[q * 8 + 7] = fmaf(gamma, v.y, acc[q * 8 + 7]);
        }
    }
    float sd = 1.0f / g_dinv[node];      // sqrt(deg)
    float mx = -1e30f;
    #pragma unroll
    for (int c = 0; c < NCLS; c++) { acc[c] *= sd; mx = fmaxf(mx, acc[c]); }
    float s = 0.f;
    #pragma unroll
    for (int c = 0; c < NCLS; c++) s += expf(acc[c] - mx);
    float l = mx + logf(s);
    float4* q = (float4*)(out + (size_t)node * NCLS);
    #pragma unroll
    for (int i = 0; i < NCLS / 4; i++) {
        float4 w;
        w.x = acc[4 * i]     - l; w.y = acc[4 * i + 1] - l;
        w.z = acc[4 * i + 2] - l; w.w = acc[4 * i + 3] - l;
        q[i] = w;
    }
}

extern "C" void kernel_launch(void* const* d_in, const int* in_sizes, int n_in,
                              void* d_out, int out_size) {
    const float* x    = (const float*)d_in[0];
    const int*   ei   = (const int*)d_in[1];     // int32 or int64 (auto-detected)
    const float* w1   = (const float*)d_in[2];
    const float* b1   = (const float*)d_in[3];
    const float* w2   = (const float*)d_in[4];
    const float* b2   = (const float*)d_in[5];
    const float* temp = (const float*)d_in[6];
    float* out = (float*)d_out;

    int nb_nodes = (N_NODESC + 255) / 256;
    int nb_edges = (N_EDGESC + 255) / 256;

    k_detect<<<1, 32>>>(ei);                                   // 1
    k_zero<<<nb_nodes, 256>>>();                               // 2
    k_count<<<nb_edges, 256>>>(ei);                            // 3
    k_mlp1<<<(N_NODESC + BM - 1) / BM, 256>>>(x, w1, b1);      // 4  (profiled slot)
    k_scan1<<<NSB, SCAN_B>>>();                                // 5
    k_scan2p<<<1, 256>>>();                                    // 6
    k_scan3<<<nb_nodes, 256>>>();                              // 7
    k_scatter<<<nb_edges, 256>>>(ei);                          // 8
    k_mlp2<<<(N_NODESC + 127) / 128, 128>>>(w2, b2);           // 9
    for (int k = 0; k < KPROP; k++)
        k_gather<<<(N_NODESC * 5 + 319) / 320, 320>>>(k);      // 10..19
    k_final<<<nb_nodes, 256>>>(temp, out);                     // 20
}